// round 6
// baseline (speedup 1.0000x reference)
#include <cuda_runtime.h>
#include <cuda_bf16.h>
#include <cuda_fp16.h>
#include <mma.h>
using namespace nvcuda;

#define NN 50000
#define EE 800000
#define NFD 64
#define EFD 32
#define HH 96
#define OUTD 64
#define LL 4
#define GG 64
#define NH (NN*HH)
typedef __nv_bfloat16 bf;

// ------------------------------ scratch ------------------------------------
__device__ float d_f[4*NH];                                   // h, h2, PT, PS
__device__ bf d_bb[2*NN*NFD + 10*NH + 4*GG*HH + 2*EE*EFD];    // split pairs
__device__ __half d_pe[(size_t)LL*EE*HH];                     // per-layer ea@W1c
__device__ int d_i[NN + (NN+1) + NN + EE + EE + (GG+1) + (GG+1)];

__device__ __forceinline__ void split1(float x, bf& h, bf& l) {
    h = __float2bfloat16_rn(x);
    l = __float2bfloat16_rn(x - __bfloat162float(h));
}

// ------------------------------ setup --------------------------------------
__global__ void hist_kernel(const int* __restrict__ idx, int* __restrict__ cnt, int n) {
    int i = blockIdx.x*blockDim.x + threadIdx.x;
    if (i < n) atomicAdd(&cnt[idx[i]], 1);
}
__global__ void scatter_kernel(const int* __restrict__ src, const int* __restrict__ tgt,
                               int* __restrict__ cursor, int* __restrict__ srcs,
                               int* __restrict__ eids, int n) {
    int e = blockIdx.x*blockDim.x + threadIdx.x;
    if (e < n) { int p = atomicAdd(&cursor[tgt[e]], 1); srcs[p] = src[e]; eids[p] = e; }
}
__global__ void scan_kernel(const int* __restrict__ in, int* __restrict__ out, int n) {
    __shared__ int sums[32];
    int lane = threadIdx.x & 31, wid = threadIdx.x >> 5, nwarp = blockDim.x >> 5;
    int offset = 0;
    for (int base = 0; base < n; base += blockDim.x) {
        int i = base + threadIdx.x;
        int v = (i < n) ? in[i] : 0, x = v;
        #pragma unroll
        for (int d = 1; d < 32; d <<= 1) { int y = __shfl_up_sync(~0u, x, d); if (lane >= d) x += y; }
        if (lane == 31) sums[wid] = x;
        __syncthreads();
        if (wid == 0) {
            int s = (lane < nwarp) ? sums[lane] : 0;
            #pragma unroll
            for (int d = 1; d < 32; d <<= 1) { int y = __shfl_up_sync(~0u, s, d); if (lane >= d) s += y; }
            sums[lane] = s;
        }
        __syncthreads();
        int warp_off = (wid > 0) ? sums[wid-1] : 0;
        if (i < n) out[i] = offset + warp_off + x - v;
        int total = sums[nwarp-1];
        __syncthreads();
        offset += total;
    }
    if (threadIdx.x == 0) out[n] = offset;
}
__global__ void split_kernel(const float* __restrict__ src, bf* __restrict__ hi,
                             bf* __restrict__ lo, int n) {
    int i = blockIdx.x*blockDim.x + threadIdx.x;
    if (i < n) { bf h, l; split1(src[i], h, l); hi[i] = h; lo[i] = l; }
}
// gather edge_attr into CSR order + split
__global__ void ea_gather_kernel(const float* __restrict__ EA, const int* __restrict__ eids,
                                 bf* __restrict__ hi, bf* __restrict__ lo, int n) {
    int idx = blockIdx.x*blockDim.x + threadIdx.x;
    if (idx < n) {
        int i = idx >> 5, f = idx & 31;
        bf h, l; split1(EA[eids[i]*EFD + f], h, l);
        hi[idx] = h; lo[idx] = l;
    }
}

// ------------------------- tensor-core GEMM --------------------------------
// C[M,Ncols] = act(A@W + b) with A = concat(A1,A2) bf16 hi/lo pairs (K1 split).
// Block 128x96, 8 warps (warp tile 32x48), K chunked by 32. 3-term split mma.
__global__ void __launch_bounds__(256) gemm_tc(
    const bf* __restrict__ A1h, const bf* __restrict__ A1l, int lda1,
    const bf* __restrict__ A2h, const bf* __restrict__ A2l, int lda2,
    int K1, int K,
    const float* __restrict__ W, int ldW, const float* __restrict__ bias,
    float* __restrict__ Cf, bf* __restrict__ Ch, bf* __restrict__ Cl,
    __half* __restrict__ Chf, int ldC,
    int M, int Ncols, int relu, const int* __restrict__ rowmask)
{
    __shared__ __align__(16) char smraw[49152];
    bf* Ah = (bf*)smraw;            // [128][40]
    bf* Al = Ah + 128*40;
    bf* Wh = Al + 128*40;           // [32][104]
    bf* Wl = Wh + 32*104;
    float* Cs = (float*)smraw;      // [128][96] epilogue (reuses staging)

    int tid = threadIdx.x, wid = tid >> 5;
    int bm0 = blockIdx.x * 128;
    int wm = (wid & 3) * 32, wn = (wid >> 2) * 48;

    wmma::fragment<wmma::accumulator,16,16,16,float> acc[2][3];
    #pragma unroll
    for (int i = 0; i < 2; i++)
        #pragma unroll
        for (int j = 0; j < 3; j++) wmma::fill_fragment(acc[i][j], 0.f);

    for (int k0 = 0; k0 < K; k0 += 32) {
        const bf *Sh, *Sl; int alda, akoff;
        if (k0 < K1) { Sh = A1h; Sl = A1l; alda = lda1; akoff = k0; }
        else         { Sh = A2h; Sl = A2l; alda = lda2; akoff = k0 - K1; }
        #pragma unroll
        for (int p = tid; p < 2048; p += 256) {
            int r = p >> 4, kc = (p & 15) << 1;
            int row = bm0 + r;
            unsigned vh = 0, vl = 0;
            if (row < M) {
                vh = *(const unsigned*)(Sh + (size_t)row*alda + akoff + kc);
                vl = *(const unsigned*)(Sl + (size_t)row*alda + akoff + kc);
            }
            *(unsigned*)&Ah[r*40 + kc] = vh;
            *(unsigned*)&Al[r*40 + kc] = vl;
        }
        #pragma unroll
        for (int p = tid; p < 1536; p += 256) {
            int kk = p / 48, nc = (p % 48) * 2;
            float w0 = 0.f, w1 = 0.f;
            if (nc < Ncols)     w0 = W[(size_t)(k0+kk)*ldW + nc];
            if (nc + 1 < Ncols) w1 = W[(size_t)(k0+kk)*ldW + nc + 1];
            bf h0, l0, h1, l1; split1(w0, h0, l0); split1(w1, h1, l1);
            Wh[kk*104 + nc] = h0; Wh[kk*104 + nc + 1] = h1;
            Wl[kk*104 + nc] = l0; Wl[kk*104 + nc + 1] = l1;
        }
        __syncthreads();
        #pragma unroll
        for (int ks = 0; ks < 32; ks += 16) {
            wmma::fragment<wmma::matrix_a,16,16,16,bf,wmma::row_major> ah[2], al2[2];
            wmma::fragment<wmma::matrix_b,16,16,16,bf,wmma::row_major> bh[3], bl[3];
            #pragma unroll
            for (int i = 0; i < 2; i++) {
                wmma::load_matrix_sync(ah[i],  &Ah[(wm + i*16)*40 + ks], 40);
                wmma::load_matrix_sync(al2[i], &Al[(wm + i*16)*40 + ks], 40);
            }
            #pragma unroll
            for (int j = 0; j < 3; j++) {
                wmma::load_matrix_sync(bh[j], &Wh[ks*104 + wn + j*16], 104);
                wmma::load_matrix_sync(bl[j], &Wl[ks*104 + wn + j*16], 104);
            }
            #pragma unroll
            for (int i = 0; i < 2; i++)
                #pragma unroll
                for (int j = 0; j < 3; j++) {
                    wmma::mma_sync(acc[i][j], ah[i],  bh[j], acc[i][j]);
                    wmma::mma_sync(acc[i][j], ah[i],  bl[j], acc[i][j]);
                    wmma::mma_sync(acc[i][j], al2[i], bh[j], acc[i][j]);
                }
        }
        __syncthreads();
    }
    #pragma unroll
    for (int i = 0; i < 2; i++)
        #pragma unroll
        for (int j = 0; j < 3; j++)
            wmma::store_matrix_sync(&Cs[(wm + i*16)*96 + wn + j*16], acc[i][j], 96,
                                    wmma::mem_row_major);
    __syncthreads();
    for (int p = tid; p < 128*96; p += 256) {
        int r = p / 96, c = p - r*96;
        int row = bm0 + r;
        if (row >= M || c >= Ncols) continue;
        float v = Cs[p];
        if (bias) v += bias[c];
        if (relu) v = fmaxf(v, 0.f);
        if (rowmask && rowmask[row] == 0) v = 0.f;
        size_t o = (size_t)row*ldC + c;
        if (Cf) Cf[o] = v;
        if (Ch) { bf h, l; split1(v, h, l); Ch[o] = h; Cl[o] = l; }
        if (Chf) Chf[o] = __float2half(v);
    }
}

// ---------------------------- edge aggregate -------------------------------
// warp per node: AGG[n] = mean_e relu(PT[n] + PS[src] + pe[i]); outputs bf16 split
__global__ void __launch_bounds__(256) edge_tc(
    const float* __restrict__ PT, const float* __restrict__ PS,
    const __half* __restrict__ pe,
    const int* __restrict__ rowptr, const int* __restrict__ srcs,
    bf* __restrict__ aggh, bf* __restrict__ aggl, int n) {
    int lane = threadIdx.x & 31, node = blockIdx.x*8 + (threadIdx.x >> 5);
    if (node >= n) return;
    int beg = rowptr[node], end = rowptr[node+1];
    float pt0 = PT[node*96+lane], pt1 = PT[node*96+lane+32], pt2 = PT[node*96+lane+64];
    float a0 = 0.f, a1 = 0.f, a2 = 0.f;
    for (int i = beg; i < end; i++) {
        int s = srcs[i];
        const __half* pr = pe + (size_t)i*96;
        float v0 = pt0 + PS[s*96+lane]    + __half2float(pr[lane]);
        float v1 = pt1 + PS[s*96+lane+32] + __half2float(pr[lane+32]);
        float v2 = pt2 + PS[s*96+lane+64] + __half2float(pr[lane+64]);
        a0 += fmaxf(v0, 0.f); a1 += fmaxf(v1, 0.f); a2 += fmaxf(v2, 0.f);
    }
    float inv = 1.f / (float)max(end - beg, 1);
    bf h, l;
    split1(a0*inv, h, l); aggh[node*96+lane]    = h; aggl[node*96+lane]    = l;
    split1(a1*inv, h, l); aggh[node*96+lane+32] = h; aggl[node*96+lane+32] = l;
    split1(a2*inv, h, l); aggh[node*96+lane+64] = h; aggl[node*96+lane+64] = l;
}

__global__ void pool_kernel(const float* __restrict__ h, const int* __restrict__ gstart,
                            bf* __restrict__ gmh, bf* __restrict__ gml) {
    int g = blockIdx.x, f = threadIdx.x;
    int beg = gstart[g], end = gstart[g+1];
    float s = 0.f;
    for (int r = beg; r < end; r++) s += h[r*96 + f];
    s /= (float)max(end - beg, 1);
    bf hh, ll; split1(s, hh, ll);
    gmh[g*96+f] = hh; gml[g*96+f] = ll;
}

// ------------------------------- host --------------------------------------
static void G(const bf* A1h, const bf* A1l, int lda1,
              const bf* A2h, const bf* A2l, int lda2, int K1, int K,
              const float* W, int ldW, const float* bias,
              float* Cf, bf* Ch, bf* Cl, __half* Chf, int ldC,
              int M, int N, int relu, const int* mask) {
    gemm_tc<<<(M + 127)/128, 256>>>(A1h, A1l, lda1, A2h, A2l, lda2, K1, K,
                                    W, ldW, bias, Cf, Ch, Cl, Chf, ldC, M, N, relu, mask);
}

extern "C" void kernel_launch(void* const* d_in, const int* in_sizes, int n_in,
                              void* d_out, int out_size) {
    const float* x          = (const float*)d_in[0];
    const float* edge_attr  = (const float*)d_in[1];
    const int*   edge_index = (const int*)d_in[2];
    const int*   batch      = (const int*)d_in[3];
    const float* emb_w1 = (const float*)d_in[4];  const float* emb_b1 = (const float*)d_in[5];
    const float* emb_w2 = (const float*)d_in[6];  const float* emb_b2 = (const float*)d_in[7];
    const float* msg_w1 = (const float*)d_in[8];  const float* msg_b1 = (const float*)d_in[9];
    const float* msg_w2 = (const float*)d_in[10]; const float* msg_b2 = (const float*)d_in[11];
    const float* upd_w1 = (const float*)d_in[12]; const float* upd_b1 = (const float*)d_in[13];
    const float* upd_w2 = (const float*)d_in[14]; const float* upd_b2 = (const float*)d_in[15];
    const float* head_w1 = (const float*)d_in[16]; const float* head_b1 = (const float*)d_in[17];
    const float* head_w2 = (const float*)d_in[18]; const float* head_b2 = (const float*)d_in[19];

    float* f = nullptr; bf* bb = nullptr; __half* pe = nullptr; int* ib = nullptr;
    cudaGetSymbolAddress((void**)&f, d_f);
    cudaGetSymbolAddress((void**)&bb, d_bb);
    cudaGetSymbolAddress((void**)&pe, d_pe);
    cudaGetSymbolAddress((void**)&ib, d_i);

    float* h   = f;          float* h2 = f + NH;
    float* PT  = f + 2*NH;   float* PS = f + 3*NH;

    bf* xh = bb;             bf* xl = xh + NN*NFD;
    bf* th = xl + NN*NFD;    bf* tl = th + NH;
    bf* hh_ = tl + NH;       bf* hl_ = hh_ + NH;
    bf* h2h = hl_ + NH;      bf* h2l = h2h + NH;
    bf* agh = h2l + NH;      bf* agl = agh + NH;
    bf* amh = agl + NH;      bf* aml = amh + NH;
    bf* gmh = aml + NH;      bf* gml = gmh + GG*HH;
    bf* ghh = gml + GG*HH;   bf* ghl = ghh + GG*HH;
    bf* eah = ghl + GG*HH;   bf* eal = eah + EE*EFD;

    int* deg = ib;               int* rowptr = deg + NN;
    int* cursor = rowptr + NN+1; int* srcs = cursor + NN;
    int* eids = srcs + EE;       int* gcnt = eids + EE;
    int* gstart = gcnt + GG+1;

    const int* src = edge_index;
    const int* tgt = edge_index + EE;

    // --- CSR by tgt + graph boundaries ---
    cudaMemsetAsync(deg, 0, NN*sizeof(int));
    cudaMemsetAsync(gcnt, 0, (GG+1)*sizeof(int));
    hist_kernel<<<(EE+255)/256, 256>>>(tgt, deg, EE);
    scan_kernel<<<1, 1024>>>(deg, rowptr, NN);
    cudaMemcpyAsync(cursor, rowptr, NN*sizeof(int), cudaMemcpyDeviceToDevice);
    scatter_kernel<<<(EE+255)/256, 256>>>(src, tgt, cursor, srcs, eids, EE);
    hist_kernel<<<(NN+255)/256, 256>>>(batch, gcnt, NN);
    scan_kernel<<<1, 1024>>>(gcnt, gstart, GG);

    // --- splits + per-layer edge projections Pe = ea_csr @ W1c (all 4 upfront) ---
    split_kernel<<<(NN*NFD+255)/256, 256>>>(x, xh, xl, NN*NFD);
    ea_gather_kernel<<<(EE*EFD+255)/256, 256>>>(edge_attr, eids, eah, eal, EE*EFD);
    for (int l = 0; l < LL; l++) {
        const float* W1c = msg_w1 + (size_t)l*(2*HH+EFD)*HH + 2*HH*HH;
        G(eah, eal, EFD, nullptr, nullptr, 0, EFD, EFD, W1c, HH, nullptr,
          nullptr, nullptr, nullptr, pe + (size_t)l*EE*HH, HH, EE, HH, 0, nullptr);
    }

    // --- embed ---
    G(xh, xl, NFD, nullptr, nullptr, 0, NFD, NFD, emb_w1, HH, emb_b1,
      nullptr, th, tl, nullptr, HH, NN, HH, 1, nullptr);
    G(th, tl, HH, nullptr, nullptr, 0, HH, HH, emb_w2, HH, emb_b2,
      h, hh_, hl_, nullptr, HH, NN, HH, 0, nullptr);

    float* hcf = h;  bf* hch = hh_; bf* hcl = hl_;
    float* hnf = h2; bf* hnh = h2h; bf* hnl = h2l;
    for (int l = 0; l < LL; l++) {
        const float* mw1 = msg_w1 + (size_t)l*(2*HH+EFD)*HH;
        G(hch, hcl, HH, nullptr, nullptr, 0, HH, HH, mw1, HH, msg_b1 + l*HH,
          PT, nullptr, nullptr, nullptr, HH, NN, HH, 0, nullptr);
        G(hch, hcl, HH, nullptr, nullptr, 0, HH, HH, mw1 + HH*HH, HH, nullptr,
          PS, nullptr, nullptr, nullptr, HH, NN, HH, 0, nullptr);
        edge_tc<<<(NN+7)/8, 256>>>(PT, PS, pe + (size_t)l*EE*HH, rowptr, srcs, agh, agl, NN);
        G(agh, agl, HH, nullptr, nullptr, 0, HH, HH, msg_w2 + l*HH*HH, HH, msg_b2 + l*HH,
          nullptr, amh, aml, nullptr, HH, NN, HH, 0, deg);
        G(hch, hcl, HH, amh, aml, HH, HH, 2*HH, upd_w1 + l*2*HH*HH, HH, upd_b1 + l*HH,
          nullptr, th, tl, nullptr, HH, NN, HH, 1, nullptr);
        G(th, tl, HH, nullptr, nullptr, 0, HH, HH, upd_w2 + l*HH*HH, HH, upd_b2 + l*HH,
          hnf, hnh, hnl, nullptr, HH, NN, HH, 0, nullptr);
        float* tf = hcf; hcf = hnf; hnf = tf;
        bf* t1 = hch; hch = hnh; hnh = t1;
        bf* t2 = hcl; hcl = hnl; hnl = t2;
    }

    // --- pool + head ---
    pool_kernel<<<GG, HH>>>(hcf, gstart, gmh, gml);
    G(gmh, gml, HH, nullptr, nullptr, 0, HH, HH, head_w1, HH, head_b1,
      nullptr, ghh, ghl, nullptr, HH, GG, HH, 1, nullptr);
    G(ghh, ghl, HH, nullptr, nullptr, 0, HH, HH, head_w2, OUTD, head_b2,
      (float*)d_out, nullptr, nullptr, nullptr, OUTD, GG, OUTD, 0, nullptr);
}

// round 7
// speedup vs baseline: 1.5026x; 1.5026x over previous
#include <cuda_runtime.h>
#include <cuda_bf16.h>
#include <mma.h>
using namespace nvcuda;
typedef __nv_bfloat16 bf;

#define NN 50000
#define EE 800000
#define NFD 64
#define EFD 32
#define HH 96
#define OUTD 64
#define LL 4
#define GG 64
#define NH (NN*HH)

// ------------------------------ scratch ------------------------------------
// fp32: PT, PS, AGG
__device__ float d_f[3*NH];
// packed bf16 hi/lo pairs (uint32: low16=hi, high16=lo):
// xp[NN*NFD], hp[NH], h2p[NH], tp[NH], amp[NH], gmp[GG*HH], ghp[GG*HH], eap[EE*EFD]
__device__ unsigned d_p[NN*NFD + 4*NH + 2*GG*HH + EE*EFD];
// deg[NN], rowptr[NN+1], cursor[NN], srcs[EE], eids[EE], ctgt[EE], gcnt[GG+1], gstart[GG+1]
__device__ int d_i[NN + (NN+1) + NN + 3*EE + 2*(GG+1)];

__device__ __forceinline__ unsigned packsplit(float x) {
    bf h = __float2bfloat16_rn(x);
    bf l = __float2bfloat16_rn(x - __bfloat162float(h));
    return ((unsigned)__bfloat16_as_ushort(l) << 16) | (unsigned)__bfloat16_as_ushort(h);
}
__device__ __forceinline__ void split1(float x, bf& h, bf& l) {
    h = __float2bfloat16_rn(x);
    l = __float2bfloat16_rn(x - __bfloat162float(h));
}

// ------------------------------ setup --------------------------------------
__global__ void hist_kernel(const int* __restrict__ idx, int* __restrict__ cnt, int n) {
    int i = blockIdx.x*blockDim.x + threadIdx.x;
    if (i < n) atomicAdd(&cnt[idx[i]], 1);
}
__global__ void scatter_kernel(const int* __restrict__ src, const int* __restrict__ tgt,
                               int* __restrict__ cursor, int* __restrict__ srcs,
                               int* __restrict__ eids, int* __restrict__ ctgt, int n) {
    int e = blockIdx.x*blockDim.x + threadIdx.x;
    if (e < n) {
        int t = tgt[e];
        int p = atomicAdd(&cursor[t], 1);
        srcs[p] = src[e]; eids[p] = e; ctgt[p] = t;
    }
}
__global__ void scan_kernel(const int* __restrict__ in, int* __restrict__ out, int n) {
    __shared__ int sums[32];
    int lane = threadIdx.x & 31, wid = threadIdx.x >> 5, nwarp = blockDim.x >> 5;
    int offset = 0;
    for (int base = 0; base < n; base += blockDim.x) {
        int i = base + threadIdx.x;
        int v = (i < n) ? in[i] : 0, x = v;
        #pragma unroll
        for (int d = 1; d < 32; d <<= 1) { int y = __shfl_up_sync(~0u, x, d); if (lane >= d) x += y; }
        if (lane == 31) sums[wid] = x;
        __syncthreads();
        if (wid == 0) {
            int s = (lane < nwarp) ? sums[lane] : 0;
            #pragma unroll
            for (int d = 1; d < 32; d <<= 1) { int y = __shfl_up_sync(~0u, s, d); if (lane >= d) s += y; }
            sums[lane] = s;
        }
        __syncthreads();
        int warp_off = (wid > 0) ? sums[wid-1] : 0;
        if (i < n) out[i] = offset + warp_off + x - v;
        int total = sums[nwarp-1];
        __syncthreads();
        offset += total;
    }
    if (threadIdx.x == 0) out[n] = offset;
}
__global__ void split_kernel(const float* __restrict__ s, unsigned* __restrict__ p, int n) {
    int i = blockIdx.x*blockDim.x + threadIdx.x;
    if (i < n) p[i] = packsplit(s[i]);
}
__global__ void ea_gather_kernel(const float* __restrict__ EA, const int* __restrict__ eids,
                                 unsigned* __restrict__ eap, int n) {
    int idx = blockIdx.x*blockDim.x + threadIdx.x;
    if (idx < n) {
        int i = idx >> 5, f = idx & 31;
        eap[idx] = packsplit(EA[(size_t)eids[i]*EFD + f]);
    }
}

// ------------------------- tensor-core GEMM --------------------------------
// C = act(A@W + b). A: packed-pair concat(A1p,A2p) OR fp32 Afp scaled by 1/deg.
// blockIdx.y selects (Wa,biasa,Cfa,Cpa) vs (Wb,biasb,Cfb,Cpb) (dual-output mode).
// Block 128x96, 8 warps (32x48 warp tile), K in 32-chunks, 3-term split mma.
__global__ void __launch_bounds__(256) gemm_tc(
    const unsigned* __restrict__ A1p, int lda1,
    const unsigned* __restrict__ A2p, int lda2, int K1, int K,
    const float* __restrict__ Afp, const int* __restrict__ Adeg,
    const float* __restrict__ Wa, const float* __restrict__ Wb,
    const float* __restrict__ biasa, const float* __restrict__ biasb,
    float* __restrict__ Cfa, float* __restrict__ Cfb,
    unsigned* __restrict__ Cpa, unsigned* __restrict__ Cpb,
    int ldC, int M, int Ncols, int relu, const int* __restrict__ rowmask)
{
    __shared__ __align__(16) char smraw[49152];
    bf* Ah = (bf*)smraw;            // [128][40]
    bf* Al = Ah + 128*40;
    bf* Wh = Al + 128*40;           // [32][104]
    bf* Wl = Wh + 32*104;
    float* Cs = (float*)smraw;      // [128][96] epilogue

    const float* W    = blockIdx.y ? Wb : Wa;
    const float* bias = blockIdx.y ? biasb : biasa;
    float*    Cf = blockIdx.y ? Cfb : Cfa;
    unsigned* Cp = blockIdx.y ? Cpb : Cpa;

    int tid = threadIdx.x, wid = tid >> 5;
    int bm0 = blockIdx.x * 128;
    int wm = (wid & 3) * 32, wn = (wid >> 2) * 48;

    wmma::fragment<wmma::accumulator,16,16,16,float> acc[2][3];
    #pragma unroll
    for (int i = 0; i < 2; i++)
        #pragma unroll
        for (int j = 0; j < 3; j++) wmma::fill_fragment(acc[i][j], 0.f);

    for (int k0 = 0; k0 < K; k0 += 32) {
        if (Afp) {
            #pragma unroll
            for (int p = tid; p < 2048; p += 256) {
                int r = p >> 4, kc = (p & 15) << 1;
                int row = bm0 + r;
                float v0 = 0.f, v1 = 0.f;
                if (row < M) {
                    float rs = 1.f / (float)max(Adeg[row], 1);
                    const float* a = Afp + (size_t)row*lda1 + k0 + kc;
                    v0 = a[0] * rs; v1 = a[1] * rs;
                }
                bf h0, l0, h1, l1; split1(v0, h0, l0); split1(v1, h1, l1);
                Ah[r*40+kc] = h0; Ah[r*40+kc+1] = h1;
                Al[r*40+kc] = l0; Al[r*40+kc+1] = l1;
            }
        } else {
            const unsigned* Sp; int alda, akoff;
            if (k0 < K1) { Sp = A1p; alda = lda1; akoff = k0; }
            else         { Sp = A2p; alda = lda2; akoff = k0 - K1; }
            #pragma unroll
            for (int p = tid; p < 2048; p += 256) {
                int r = p >> 4, kc = (p & 15) << 1;
                int row = bm0 + r;
                uint2 v = make_uint2(0u, 0u);
                if (row < M) v = *(const uint2*)(Sp + (size_t)row*alda + akoff + kc);
                *(unsigned*)&Ah[r*40+kc] = __byte_perm(v.x, v.y, 0x5410);
                *(unsigned*)&Al[r*40+kc] = __byte_perm(v.x, v.y, 0x7632);
            }
        }
        #pragma unroll
        for (int p = tid; p < 1536; p += 256) {
            int kk = p / 48, nc = (p % 48) * 2;
            float w0 = 0.f, w1 = 0.f;
            if (nc < Ncols)     w0 = W[(size_t)(k0+kk)*Ncols + nc];
            if (nc + 1 < Ncols) w1 = W[(size_t)(k0+kk)*Ncols + nc + 1];
            bf h0, l0, h1, l1; split1(w0, h0, l0); split1(w1, h1, l1);
            Wh[kk*104+nc] = h0; Wh[kk*104+nc+1] = h1;
            Wl[kk*104+nc] = l0; Wl[kk*104+nc+1] = l1;
        }
        __syncthreads();
        #pragma unroll
        for (int ks = 0; ks < 32; ks += 16) {
            wmma::fragment<wmma::matrix_a,16,16,16,bf,wmma::row_major> ah[2], al2[2];
            wmma::fragment<wmma::matrix_b,16,16,16,bf,wmma::row_major> bh[3], bl[3];
            #pragma unroll
            for (int i = 0; i < 2; i++) {
                wmma::load_matrix_sync(ah[i],  &Ah[(wm + i*16)*40 + ks], 40);
                wmma::load_matrix_sync(al2[i], &Al[(wm + i*16)*40 + ks], 40);
            }
            #pragma unroll
            for (int j = 0; j < 3; j++) {
                wmma::load_matrix_sync(bh[j], &Wh[ks*104 + wn + j*16], 104);
                wmma::load_matrix_sync(bl[j], &Wl[ks*104 + wn + j*16], 104);
            }
            #pragma unroll
            for (int i = 0; i < 2; i++)
                #pragma unroll
                for (int j = 0; j < 3; j++) {
                    wmma::mma_sync(acc[i][j], ah[i],  bh[j], acc[i][j]);
                    wmma::mma_sync(acc[i][j], ah[i],  bl[j], acc[i][j]);
                    wmma::mma_sync(acc[i][j], al2[i], bh[j], acc[i][j]);
                }
        }
        __syncthreads();
    }
    #pragma unroll
    for (int i = 0; i < 2; i++)
        #pragma unroll
        for (int j = 0; j < 3; j++)
            wmma::store_matrix_sync(&Cs[(wm + i*16)*96 + wn + j*16], acc[i][j], 96,
                                    wmma::mem_row_major);
    __syncthreads();
    for (int p = tid; p < 128*96; p += 256) {
        int r = p / 96, c = p - r*96;
        int row = bm0 + r;
        if (row >= M || c >= Ncols) continue;
        float v = Cs[p];
        if (bias) v += bias[c];
        if (relu) v = fmaxf(v, 0.f);
        if (rowmask && rowmask[row] == 0) v = 0.f;
        size_t o = (size_t)row*ldC + c;
        if (Cf) Cf[o] = v;
        if (Cp) Cp[o] = packsplit(v);
    }
}

// ------------------------- fused edge kernel --------------------------------
// Block = 128 contiguous CSR edges. Phase 1: pe = ea@W1c via TC into smem.
// Phase 2: run-length aggregate relu(PT[tgt]+PS[src]+pe) -> atomicAdd AGG (sum).
__global__ void __launch_bounds__(256) edge_fused(
    const unsigned* __restrict__ eap, const float* __restrict__ W1c,
    const float* __restrict__ PT, const float* __restrict__ PS,
    const int* __restrict__ csrc, const int* __restrict__ ctgt,
    float* __restrict__ AGG)
{
    __shared__ __align__(16) char smraw[49152];
    bf* Ah = (bf*)smraw;            // [128][40]
    bf* Al = Ah + 128*40;
    bf* Wh = Al + 128*40;           // [32][104]
    bf* Wl = Wh + 32*104;
    float* pes = (float*)smraw;     // [128][96]

    int tid = threadIdx.x, wid = tid >> 5, lane = tid & 31;
    int e0 = blockIdx.x * 128;
    int wm = (wid & 3) * 32, wn = (wid >> 2) * 48;

    #pragma unroll
    for (int p = tid; p < 2048; p += 256) {
        int r = p >> 4, kc = (p & 15) << 1;
        uint2 v = *(const uint2*)(eap + (size_t)(e0 + r)*EFD + kc);
        *(unsigned*)&Ah[r*40+kc] = __byte_perm(v.x, v.y, 0x5410);
        *(unsigned*)&Al[r*40+kc] = __byte_perm(v.x, v.y, 0x7632);
    }
    #pragma unroll
    for (int p = tid; p < 1536; p += 256) {
        int kk = p / 48, nc = (p % 48) * 2;
        float w0 = W1c[kk*96 + nc], w1 = W1c[kk*96 + nc + 1];
        bf h0, l0, h1, l1; split1(w0, h0, l0); split1(w1, h1, l1);
        Wh[kk*104+nc] = h0; Wh[kk*104+nc+1] = h1;
        Wl[kk*104+nc] = l0; Wl[kk*104+nc+1] = l1;
    }
    __syncthreads();

    wmma::fragment<wmma::accumulator,16,16,16,float> acc[2][3];
    #pragma unroll
    for (int i = 0; i < 2; i++)
        #pragma unroll
        for (int j = 0; j < 3; j++) wmma::fill_fragment(acc[i][j], 0.f);
    #pragma unroll
    for (int ks = 0; ks < 32; ks += 16) {
        wmma::fragment<wmma::matrix_a,16,16,16,bf,wmma::row_major> ah[2], al2[2];
        wmma::fragment<wmma::matrix_b,16,16,16,bf,wmma::row_major> bh[3], bl[3];
        #pragma unroll
        for (int i = 0; i < 2; i++) {
            wmma::load_matrix_sync(ah[i],  &Ah[(wm + i*16)*40 + ks], 40);
            wmma::load_matrix_sync(al2[i], &Al[(wm + i*16)*40 + ks], 40);
        }
        #pragma unroll
        for (int j = 0; j < 3; j++) {
            wmma::load_matrix_sync(bh[j], &Wh[ks*104 + wn + j*16], 104);
            wmma::load_matrix_sync(bl[j], &Wl[ks*104 + wn + j*16], 104);
        }
        #pragma unroll
        for (int i = 0; i < 2; i++)
            #pragma unroll
            for (int j = 0; j < 3; j++) {
                wmma::mma_sync(acc[i][j], ah[i],  bh[j], acc[i][j]);
                wmma::mma_sync(acc[i][j], ah[i],  bl[j], acc[i][j]);
                wmma::mma_sync(acc[i][j], al2[i], bh[j], acc[i][j]);
            }
    }
    __syncthreads();
    #pragma unroll
    for (int i = 0; i < 2; i++)
        #pragma unroll
        for (int j = 0; j < 3; j++)
            wmma::store_matrix_sync(&pes[(wm + i*16)*96 + wn + j*16], acc[i][j], 96,
                                    wmma::mem_row_major);
    __syncthreads();

    // phase 2: each warp aggregates 16 edges (uniform control across lanes)
    int base = wid * 16;
    int cur = -1;
    float a0 = 0.f, a1 = 0.f, a2 = 0.f, p0 = 0.f, p1 = 0.f, p2 = 0.f;
    for (int j = 0; j < 16; j++) {
        int i = e0 + base + j;
        int t = ctgt[i], s = csrc[i];
        if (t != cur) {
            if (cur >= 0) {
                atomicAdd(&AGG[cur*96 + lane],      a0);
                atomicAdd(&AGG[cur*96 + lane + 32], a1);
                atomicAdd(&AGG[cur*96 + lane + 64], a2);
            }
            cur = t; a0 = a1 = a2 = 0.f;
            p0 = PT[t*96 + lane]; p1 = PT[t*96 + lane + 32]; p2 = PT[t*96 + lane + 64];
        }
        const float* pr = &pes[(base + j)*96];
        a0 += fmaxf(p0 + PS[s*96 + lane]      + pr[lane],      0.f);
        a1 += fmaxf(p1 + PS[s*96 + lane + 32] + pr[lane + 32], 0.f);
        a2 += fmaxf(p2 + PS[s*96 + lane + 64] + pr[lane + 64], 0.f);
    }
    if (cur >= 0) {
        atomicAdd(&AGG[cur*96 + lane],      a0);
        atomicAdd(&AGG[cur*96 + lane + 32], a1);
        atomicAdd(&AGG[cur*96 + lane + 64], a2);
    }
}

__global__ void pool_kernel(const unsigned* __restrict__ hp, const int* __restrict__ gstart,
                            unsigned* __restrict__ gmp) {
    int g = blockIdx.x, f = threadIdx.x;
    int beg = gstart[g], end = gstart[g+1];
    float s = 0.f;
    for (int r = beg; r < end; r++) {
        unsigned u = hp[(size_t)r*96 + f];
        s += __bfloat162float(__ushort_as_bfloat16((unsigned short)(u & 0xffff)))
           + __bfloat162float(__ushort_as_bfloat16((unsigned short)(u >> 16)));
    }
    s /= (float)max(end - beg, 1);
    gmp[g*96 + f] = packsplit(s);
}

// ------------------------------- host --------------------------------------
static void G(const unsigned* A1p, int lda1, const unsigned* A2p, int lda2,
              int K1, int K, const float* Afp, const int* Adeg,
              const float* Wa, const float* Wb, const float* ba, const float* bb,
              float* Cfa, float* Cfb, unsigned* Cpa, unsigned* Cpb,
              int ldC, int M, int N, int relu, const int* mask) {
    dim3 grid((M + 127)/128, Wb ? 2 : 1);
    gemm_tc<<<grid, 256>>>(A1p, lda1, A2p, lda2, K1, K, Afp, Adeg, Wa, Wb, ba, bb,
                           Cfa, Cfb, Cpa, Cpb, ldC, M, N, relu, mask);
}

extern "C" void kernel_launch(void* const* d_in, const int* in_sizes, int n_in,
                              void* d_out, int out_size) {
    const float* x          = (const float*)d_in[0];
    const float* edge_attr  = (const float*)d_in[1];
    const int*   edge_index = (const int*)d_in[2];
    const int*   batch      = (const int*)d_in[3];
    const float* emb_w1 = (const float*)d_in[4];  const float* emb_b1 = (const float*)d_in[5];
    const float* emb_w2 = (const float*)d_in[6];  const float* emb_b2 = (const float*)d_in[7];
    const float* msg_w1 = (const float*)d_in[8];  const float* msg_b1 = (const float*)d_in[9];
    const float* msg_w2 = (const float*)d_in[10]; const float* msg_b2 = (const float*)d_in[11];
    const float* upd_w1 = (const float*)d_in[12]; const float* upd_b1 = (const float*)d_in[13];
    const float* upd_w2 = (const float*)d_in[14]; const float* upd_b2 = (const float*)d_in[15];
    const float* head_w1 = (const float*)d_in[16]; const float* head_b1 = (const float*)d_in[17];
    const float* head_w2 = (const float*)d_in[18]; const float* head_b2 = (const float*)d_in[19];

    float* f = nullptr; unsigned* pp = nullptr; int* ib = nullptr;
    cudaGetSymbolAddress((void**)&f, d_f);
    cudaGetSymbolAddress((void**)&pp, d_p);
    cudaGetSymbolAddress((void**)&ib, d_i);

    float* PT  = f;  float* PS = f + NH;  float* AGG = f + 2*NH;

    unsigned* xp  = pp;
    unsigned* hp  = xp + NN*NFD;
    unsigned* h2p = hp + NH;
    unsigned* tp  = h2p + NH;
    unsigned* amp = tp + NH;
    unsigned* gmp = amp + NH;
    unsigned* ghp = gmp + GG*HH;
    unsigned* eap = ghp + GG*HH;

    int* deg = ib;                int* rowptr = deg + NN;
    int* cursor = rowptr + NN+1;  int* srcs = cursor + NN;
    int* eids = srcs + EE;        int* ctgt = eids + EE;
    int* gcnt = ctgt + EE;        int* gstart = gcnt + GG+1;

    const int* src = edge_index;
    const int* tgt = edge_index + EE;

    // --- CSR by tgt + graph boundaries ---
    cudaMemsetAsync(deg, 0, NN*sizeof(int));
    cudaMemsetAsync(gcnt, 0, (GG+1)*sizeof(int));
    hist_kernel<<<(EE+255)/256, 256>>>(tgt, deg, EE);
    scan_kernel<<<1, 1024>>>(deg, rowptr, NN);
    cudaMemcpyAsync(cursor, rowptr, NN*sizeof(int), cudaMemcpyDeviceToDevice);
    scatter_kernel<<<(EE+255)/256, 256>>>(src, tgt, cursor, srcs, eids, ctgt, EE);
    hist_kernel<<<(NN+255)/256, 256>>>(batch, gcnt, NN);
    scan_kernel<<<1, 1024>>>(gcnt, gstart, GG);

    // --- input splits ---
    split_kernel<<<(NN*NFD+255)/256, 256>>>(x, xp, NN*NFD);
    ea_gather_kernel<<<(EE*EFD+255)/256, 256>>>(edge_attr, eids, eap, EE*EFD);

    // --- embed ---
    G(xp, NFD, nullptr, 0, NFD, NFD, nullptr, nullptr, emb_w1, nullptr, emb_b1, nullptr,
      nullptr, nullptr, tp, nullptr, HH, NN, HH, 1, nullptr);
    G(tp, HH, nullptr, 0, HH, HH, nullptr, nullptr, emb_w2, nullptr, emb_b2, nullptr,
      nullptr, nullptr, hp, nullptr, HH, NN, HH, 0, nullptr);

    unsigned* hc = hp;
    unsigned* hn = h2p;
    for (int l = 0; l < LL; l++) {
        const float* mw1 = msg_w1 + (size_t)l*(2*HH+EFD)*HH;
        // PT = h@W1a + b1 ; PS = h@W1b   (one dual launch)
        G(hc, HH, nullptr, 0, HH, HH, nullptr, nullptr,
          mw1, mw1 + HH*HH, msg_b1 + l*HH, nullptr,
          PT, PS, nullptr, nullptr, HH, NN, HH, 0, nullptr);
        // AGG = sum_e relu(PT[tgt]+PS[src]+ea@W1c)
        cudaMemsetAsync(AGG, 0, NH*sizeof(float));
        edge_fused<<<EE/128, 256>>>(eap, mw1 + 2*HH*HH, PT, PS, srcs, ctgt, AGG);
        // amp = (AGG/deg)@msg_w2 + msg_b2  (0 rows for deg==0)
        G(nullptr, HH, nullptr, 0, HH, HH, AGG, deg,
          msg_w2 + (size_t)l*HH*HH, nullptr, msg_b2 + l*HH, nullptr,
          nullptr, nullptr, amp, nullptr, HH, NN, HH, 0, deg);
        // update MLP
        G(hc, HH, amp, HH, HH, 2*HH, nullptr, nullptr,
          upd_w1 + (size_t)l*2*HH*HH, nullptr, upd_b1 + l*HH, nullptr,
          nullptr, nullptr, tp, nullptr, HH, NN, HH, 1, nullptr);
        G(tp, HH, nullptr, 0, HH, HH, nullptr, nullptr,
          upd_w2 + (size_t)l*HH*HH, nullptr, upd_b2 + l*HH, nullptr,
          nullptr, nullptr, hn, nullptr, HH, NN, HH, 0, nullptr);
        unsigned* t = hc; hc = hn; hn = t;
    }

    // --- pool + head ---
    pool_kernel<<<GG, HH>>>(hc, gstart, gmp);
    G(gmp, HH, nullptr, 0, HH, HH, nullptr, nullptr, head_w1, nullptr, head_b1, nullptr,
      nullptr, nullptr, ghp, nullptr, HH, GG, HH, 1, nullptr);
    G(ghp, HH, nullptr, 0, HH, HH, nullptr, nullptr, head_w2, nullptr, head_b2, nullptr,
      (float*)d_out, nullptr, nullptr, nullptr, OUTD, GG, OUTD, 0, nullptr);
}